// round 15
// baseline (speedup 1.0000x reference)
#include <cuda_runtime.h>
#include <cuda_fp16.h>
#include <cstdint>
#include <math.h>

#define BATCH 256
#define NTOK 197
#define CDIM 768
#define HEADS 12
#define DH 64
#define GRID14 14
#define M_ROWS (BATCH * NTOK)   /* 50432 = 394*128 */
#define QKV_N (3 * CDIM)        /* 2304 */
#define KTOT 768
#define ROWB (KTOT * 2)         /* 1536 bytes per fp16 row */

/* ---------------- scratch (__device__ globals; no allocs allowed) -------- */
__device__ __half g_qkv[(size_t)M_ROWS * QKV_N];     /* qkv fp16          */
__device__ __half g_xs[(size_t)M_ROWS * KTOT];       /* x fp16            */
__device__ __half g_atts[(size_t)M_ROWS * KTOT];     /* attn+conv fp16    */
__device__ __half g_wqkvs[(size_t)QKV_N * KTOT];     /* W_qkv^T fp16      */
__device__ __half g_wprojs[(size_t)CDIM * KTOT];     /* W_proj^T fp16     */

/* ---------------- helpers ------------------------------------------------- */
__device__ __forceinline__ uint32_t smem_u32(const void* p) {
    uint32_t a;
    asm("{ .reg .u64 t; cvta.to.shared.u64 t, %1; cvt.u32.u64 %0, t; }" : "=r"(a) : "l"(p));
    return a;
}
__device__ __forceinline__ uint32_t sw128(uint32_t o) { return o ^ ((o >> 3) & 0x70); }

__device__ __forceinline__ void cp16(uint32_t s, const void* g) {
    asm volatile("cp.async.cg.shared.global [%0], [%1], 16;" :: "r"(s), "l"(g));
}
__device__ __forceinline__ void ldm_x4(uint32_t* r, uint32_t a) {
    asm volatile("ldmatrix.sync.aligned.m8n8.x4.shared.b16 {%0,%1,%2,%3}, [%4];"
                 : "=r"(r[0]), "=r"(r[1]), "=r"(r[2]), "=r"(r[3]) : "r"(a));
}
__device__ __forceinline__ void ldm_x4t(uint32_t* r, uint32_t a) {
    asm volatile("ldmatrix.sync.aligned.m8n8.x4.trans.shared.b16 {%0,%1,%2,%3}, [%4];"
                 : "=r"(r[0]), "=r"(r[1]), "=r"(r[2]), "=r"(r[3]) : "r"(a));
}
__device__ __forceinline__ void mma16816(float* c, const uint32_t* a, const uint32_t* b) {
    asm volatile(
        "mma.sync.aligned.m16n8k16.row.col.f32.f16.f16.f32 "
        "{%0,%1,%2,%3}, {%4,%5,%6,%7}, {%8,%9}, {%0,%1,%2,%3};"
        : "+f"(c[0]), "+f"(c[1]), "+f"(c[2]), "+f"(c[3])
        : "r"(a[0]), "r"(a[1]), "r"(a[2]), "r"(a[3]), "r"(b[0]), "r"(b[1]));
}
__device__ __forceinline__ uint32_t pack2h(float x, float y) {
    __half2 h = __floats2half2_rn(x, y);
    return *reinterpret_cast<uint32_t*>(&h);
}
/* output-type-dispatched pair store */
__device__ __forceinline__ void store2(float* p, float a, float b) {
    *(float2*)p = make_float2(a, b);
}
__device__ __forceinline__ void store2(__half* p, float a, float b) {
    *(uint32_t*)p = pack2h(a, b);
}

/* ---------------- prep kernels -------------------------------------------- */
__global__ __launch_bounds__(256) void xpack(const float* __restrict__ in,
                                             __half* __restrict__ out, int total)
{
    int idx = blockIdx.x * 256 + threadIdx.x;
    if (idx >= total) return;
    out[idx] = __float2half_rn(in[idx]);
}

/* W [768, N] fp32 -> out [N, 768] fp16: 32x32 tiled transpose, coalesced */
__global__ __launch_bounds__(256) void wpack(const float* __restrict__ W,
                                             __half* __restrict__ out, int N)
{
    __shared__ __half tile[32][33];
    const int n0 = blockIdx.x * 32;
    const int k0 = blockIdx.y * 32;
    const int tx = threadIdx.x & 31;
    const int ty = threadIdx.x >> 5;   /* 0..7 */
#pragma unroll
    for (int i = ty; i < 32; i += 8)
        tile[tx][i] = __float2half_rn(W[(size_t)(k0 + i) * N + n0 + tx]);
    __syncthreads();
#pragma unroll
    for (int i = ty; i < 32; i += 8)
        out[(size_t)(n0 + i) * KTOT + k0 + tx] = tile[i][tx];
}

/* ---------------- fp16 GEMM: 128x64 tile, 2 warps, 4 CTAs/SM -------------- */
#define TM 128
#define TN 64
#define NSTG 12                   /* 768 / 64 */
#define RING 2
#define STG_A 16384               /* 128 rows * 128B */
#define STG_B 8192                /* 64 rows * 128B  */
#define STG (STG_A + STG_B)       /* 24576 */
#define GSMEM (RING * STG)        /* 49152 -> 4 CTAs/SM */

__device__ __forceinline__ void load_stage(uint32_t sb, int buf, int st,
                                           const char* Ag, const char* Bg, int tid)
{
    uint32_t ab = sb + buf * STG;
    const char* a0 = Ag + (size_t)st * 128;
#pragma unroll
    for (int c = tid; c < 1024; c += 64) {
        int r = c >> 3, j = c & 7;
        cp16(ab + sw128(r * 128 + j * 16), a0 + (size_t)r * ROWB + j * 16);
    }
    uint32_t bb = ab + STG_A;
    const char* b0 = Bg + (size_t)st * 128;
#pragma unroll
    for (int c = tid; c < 512; c += 64) {
        int r = c >> 3, j = c & 7;
        cp16(bb + sw128(r * 128 + j * 16), b0 + (size_t)r * ROWB + j * 16);
    }
    asm volatile("cp.async.commit_group;" ::: "memory");
}

template <typename OutT>
__global__ __launch_bounds__(64, 4) void gemm_mma(
    const __half* __restrict__ As, const __half* __restrict__ Bs,
    const float* __restrict__ bias, OutT* __restrict__ C, int Nd)
{
    extern __shared__ __align__(1024) char smc[];
    uint32_t sb = smem_u32(smc);
    const int tid = threadIdx.x;
    const size_t bm = (size_t)blockIdx.y * TM;
    const size_t bn = (size_t)blockIdx.x * TN;
    const char* Ag = (const char*)As + bm * ROWB;
    const char* Bg = (const char*)Bs + bn * ROWB;

    load_stage(sb, 0, 0, Ag, Bg, tid);

    const int warp = tid >> 5, lane = tid & 31;
    const int wm = warp * 64;

    float acc[4][8][4];
#pragma unroll
    for (int i = 0; i < 4; i++)
#pragma unroll
        for (int j = 0; j < 8; j++)
#pragma unroll
            for (int q = 0; q < 4; q++) acc[i][j][q] = 0.f;

    const int a_r = lane & 15;
    const int a_c = (lane >> 4) << 4;
    const int b_r = (lane & 7) + ((lane >> 4) << 3);
    const int b_c = ((lane >> 3) & 1) << 4;

    for (int s = 0; s < NSTG; s++) {
        const int buf = s & 1;
        asm volatile("cp.async.wait_group 0;" ::: "memory");
        __syncthreads();
        if (s + 1 < NSTG) load_stage(sb, buf ^ 1, s + 1, Ag, Bg, tid);

        uint32_t ab = sb + buf * STG;
        uint32_t bb = ab + STG_A;

#pragma unroll
        for (int t = 0; t < 4; t++) {
            uint32_t br[4][4];
#pragma unroll
            for (int j = 0; j < 4; j++) {
                int row = j * 16 + b_r;
                ldm_x4(br[j], bb + sw128(row * 128 + t * 32 + b_c));
            }
            uint32_t ar[4][4];
#pragma unroll
            for (int i = 0; i < 4; i++) {
                int row = wm + i * 16 + a_r;
                ldm_x4(ar[i], ab + sw128(row * 128 + t * 32 + a_c));
            }
#pragma unroll
            for (int i = 0; i < 4; i++)
#pragma unroll
                for (int j = 0; j < 4; j++) {
                    mma16816(acc[i][2 * j + 0], ar[i], &br[j][0]);
                    mma16816(acc[i][2 * j + 1], ar[i], &br[j][2]);
                }
        }
    }

    const int r0 = lane >> 2;
    const int c0 = (lane & 3) * 2;
    const size_t grow = bm + wm + r0;
    const int gcol = (int)bn + c0;

    float2 bv[8];
#pragma unroll
    for (int j = 0; j < 8; j++)
        bv[j] = *(const float2*)(bias + gcol + j * 8);

#pragma unroll
    for (int i = 0; i < 4; i++) {
        OutT* cp0 = C + (grow + i * 16) * Nd + gcol;
        OutT* cp1 = cp0 + (size_t)8 * Nd;
#pragma unroll
        for (int j = 0; j < 8; j++) {
            store2(cp0 + j * 8, acc[i][j][0] + bv[j].x, acc[i][j][1] + bv[j].y);
            store2(cp1 + j * 8, acc[i][j][2] + bv[j].x, acc[i][j][3] + bv[j].y);
        }
    }
}

/* ---------------- tensor-core attention + precomputed depthwise conv ------- */
/* One CTA per (b,h).  K,V staged via 16B cp.async (rows are 128B contiguous */
/* in qkv).  QK^T 1-term, PV 1-term.  Conv precomputed once per CTA.         */
/* Q fragments for strip s+4 are prefetched right after strip s's QK phase.  */
#define NPAD 208
#define ACHB (NPAD * 128)           /* 26624 */
#define WS_OFF (2 * ACHB)           /* 53248: 288 float2 conv weights */
#define BS_OFF (WS_OFF + 2304)      /* 55552: 32 float2 conv bias     */
#define CV_OFF (BS_OFF + 256)       /* 55808: conv results            */
#define CVSTRIDE 136                /* bytes per conv row */
#define ASMEM (CV_OFF + NTOK * CVSTRIDE)  /* 82600 -> 2 CTAs/SM */

__global__ __launch_bounds__(128, 2) void attn_mma(const __half* __restrict__ qkv,
                                                   const float* __restrict__ dwc_w,
                                                   const float* __restrict__ dwc_b,
                                                   __half* __restrict__ atts)
{
    extern __shared__ __align__(1024) char smem[];
    uint32_t sbase = smem_u32(smem);
    const uint32_t Ksm = sbase, Vsm = sbase + ACHB, Cv = sbase + CV_OFF;
    float2* ws2 = (float2*)(smem + WS_OFF);
    float2* bs2 = (float2*)(smem + BS_OFF);
    const int b = blockIdx.x / HEADS, h = blockIdx.x % HEADS;
    const int tid = threadIdx.x;
    const __half* base = qkv + (size_t)b * NTOK * QKV_N + h * DH;

    /* K,V rows are 128B contiguous in global -> 16B cp.async staging */
    {
        const char* kg = (const char*)(base + CDIM);
        const char* vg = (const char*)(base + 2 * CDIM);
        for (int idx = tid; idx < NTOK * 8; idx += 128) {
            int j = idx >> 3, c = idx & 7;
            uint32_t off = sw128((uint32_t)(j * 128 + c * 16));
            const char* src = (const char*)((size_t)j * (QKV_N * 2)) ;
            cp16(Ksm + off, kg + (size_t)j * (QKV_N * 2) + c * 16);
            cp16(Vsm + off, vg + (size_t)j * (QKV_N * 2) + c * 16);
            (void)src;
        }
        asm volatile("cp.async.commit_group;" ::: "memory");
    }
    /* zero pad rows 197..207 (11 rows x 8 chunks) while loads fly */
    for (int idx = tid; idx < 11 * 8; idx += 128) {
        int j = NTOK + (idx >> 3), c = idx & 7;
        uint32_t off = sw128((uint32_t)(j * 128 + c * 16));
        asm volatile("st.shared.v4.b32 [%0], {%1,%1,%1,%1};" :: "r"(Ksm + off), "r"(0u) : "memory");
        asm volatile("st.shared.v4.b32 [%0], {%1,%1,%1,%1};" :: "r"(Vsm + off), "r"(0u) : "memory");
    }
    /* conv weights/bias for this head */
    for (int i = tid; i < 288; i += 128) {
        int pair = i / 9, tap = i % 9;
        int c = h * 64 + pair * 2;
        ws2[i] = make_float2(dwc_w[(size_t)c * 9 + tap], dwc_w[(size_t)(c + 1) * 9 + tap]);
    }
    if (tid < 32) bs2[tid] = make_float2(dwc_b[h * 64 + tid * 2], dwc_b[h * 64 + tid * 2 + 1]);

    asm volatile("cp.async.wait_group 0;" ::: "memory");
    __syncthreads();

    /* cooperative conv pass: conflict-free, one result row per token m=1..196 */
    for (int idx = tid; idx < 196 * 32; idx += 128) {
        int m = 1 + (idx >> 5);
        int dp = idx & 31;
        int y = (m - 1) / GRID14, x = (m - 1) % GRID14;
        float2 cv = bs2[dp];
        const float2* wp = ws2 + dp * 9;
#pragma unroll
        for (int ky = 0; ky < 3; ky++) {
            int yy = y + ky - 1;
            if (yy < 0 || yy >= GRID14) continue;
#pragma unroll
            for (int kx = 0; kx < 3; kx++) {
                int xx = x + kx - 1;
                if (xx < 0 || xx >= GRID14) continue;
                int j = 1 + yy * GRID14 + xx;
                uint32_t vh;
                asm("ld.shared.b32 %0,[%1];" : "=r"(vh)
                    : "r"(Vsm + sw128((uint32_t)(j * 128 + dp * 4))));
                __half2 h2 = *reinterpret_cast<__half2*>(&vh);
                float2 wv = wp[ky * 3 + kx];
                cv.x = fmaf(__half2float(h2.x), wv.x, cv.x);
                cv.y = fmaf(__half2float(h2.y), wv.y, cv.y);
            }
        }
        uint32_t cw = pack2h(cv.x, cv.y);
        asm volatile("st.shared.b32 [%0], %1;"
                     :: "r"(Cv + (uint32_t)(m * CVSTRIDE + dp * 4)), "r"(cw) : "memory");
    }
    __syncthreads();

    const int lane = tid & 31, warp = tid >> 5;
    const int wst = (blockIdx.x & 1) ? (3 - warp) : warp;   /* SMSP balance */
    const int qr = lane >> 2;
    const int qc = (lane & 3) * 2;
    const int b_r = (lane & 7) + ((lane >> 4) << 3);
    const int b_c = ((lane >> 3) & 1) << 4;
    const int a_r = lane & 15;
    const int a_c = (lane >> 4) << 4;

    /* Q fragment loader (overwrites qh in place) */
    uint32_t qh[4][4];
    auto loadQ = [&](int s) {
        const int m0 = s * 16 + qr;
        const int m1 = m0 + 8;
        const int rm0 = m0 < NTOK ? m0 : NTOK - 1;
        const int rm1 = m1 < NTOK ? m1 : NTOK - 1;
        const __half* q0 = base + (size_t)rm0 * QKV_N;
        const __half* q1 = base + (size_t)rm1 * QKV_N;
#pragma unroll
        for (int kt = 0; kt < 4; kt++) {
            int c = kt * 16 + qc;
            qh[kt][0] = *(const uint32_t*)(q0 + c);
            qh[kt][1] = *(const uint32_t*)(q1 + c);
            qh[kt][2] = *(const uint32_t*)(q0 + c + 8);
            qh[kt][3] = *(const uint32_t*)(q1 + c + 8);
        }
    };
    if (wst < 13) loadQ(wst);

    for (int s = wst; s < 13; s += 4) {
        const int m0 = s * 16 + qr;
        const int m1 = m0 + 8;

        float S[26][4];
#pragma unroll
        for (int t = 0; t < 26; t++)
#pragma unroll
            for (int q = 0; q < 4; q++) S[t][q] = 0.f;

#pragma unroll
        for (int nc = 0; nc < 13; nc++) {
#pragma unroll
            for (int kt = 0; kt < 4; kt++) {
                uint32_t kb[4];
                ldm_x4(kb, Ksm + sw128((uint32_t)((nc * 16 + b_r) * 128 + kt * 32 + b_c)));
                mma16816(S[2 * nc],     qh[kt], &kb[0]);
                mma16816(S[2 * nc + 1], qh[kt], &kb[2]);
            }
        }

        /* prefetch next strip's Q now -- latency hides under softmax + PV */
        if (s + 4 < 13) loadQ(s + 4);

#pragma unroll
        for (int t = 24; t < 26; t++) {
            int j0 = t * 8 + qc;
            if (j0 >= NTOK)     S[t][0] = S[t][2] = -1e30f;
            if (j0 + 1 >= NTOK) S[t][1] = S[t][3] = -1e30f;
        }

        float mx0 = -1e30f, mx1 = -1e30f;
#pragma unroll
        for (int t = 0; t < 26; t++) {
            mx0 = fmaxf(mx0, fmaxf(S[t][0], S[t][1]));
            mx1 = fmaxf(mx1, fmaxf(S[t][2], S[t][3]));
        }
        mx0 = fmaxf(mx0, __shfl_xor_sync(0xffffffffu, mx0, 1));
        mx0 = fmaxf(mx0, __shfl_xor_sync(0xffffffffu, mx0, 2));
        mx1 = fmaxf(mx1, __shfl_xor_sync(0xffffffffu, mx1, 1));
        mx1 = fmaxf(mx1, __shfl_xor_sync(0xffffffffu, mx1, 2));
        float sum0 = 0.f, sum1 = 0.f;
#pragma unroll
        for (int t = 0; t < 26; t++) {
            S[t][0] = __expf((S[t][0] - mx0) * 0.125f);
            S[t][1] = __expf((S[t][1] - mx0) * 0.125f);
            S[t][2] = __expf((S[t][2] - mx1) * 0.125f);
            S[t][3] = __expf((S[t][3] - mx1) * 0.125f);
            sum0 += S[t][0] + S[t][1];
            sum1 += S[t][2] + S[t][3];
        }
        sum0 += __shfl_xor_sync(0xffffffffu, sum0, 1);
        sum0 += __shfl_xor_sync(0xffffffffu, sum0, 2);
        sum1 += __shfl_xor_sync(0xffffffffu, sum1, 1);
        sum1 += __shfl_xor_sync(0xffffffffu, sum1, 2);
        float inv0 = __frcp_rn(sum0), inv1 = __frcp_rn(sum1);

        float O[8][4];
#pragma unroll
        for (int t = 0; t < 8; t++)
#pragma unroll
            for (int q = 0; q < 4; q++) O[t][q] = 0.f;

#pragma unroll
        for (int jt = 0; jt < 13; jt++) {
            uint32_t ph[4];
            ph[0] = pack2h(S[2 * jt][0],     S[2 * jt][1]);
            ph[1] = pack2h(S[2 * jt][2],     S[2 * jt][3]);
            ph[2] = pack2h(S[2 * jt + 1][0], S[2 * jt + 1][1]);
            ph[3] = pack2h(S[2 * jt + 1][2], S[2 * jt + 1][3]);
#pragma unroll
            for (int dc = 0; dc < 4; dc++) {
                uint32_t vb[4];
                uint32_t rb = (uint32_t)((jt * 16 + a_r) * 128 + dc * 32 + a_c);
                ldm_x4t(vb, Vsm + sw128(rb));
                mma16816(O[2 * dc],     ph, &vb[0]);
                mma16816(O[2 * dc + 1], ph, &vb[2]);
            }
        }

        /* write rows; conv term is one smem load per 8-col group */
#pragma unroll
        for (int rsel = 0; rsel < 2; rsel++) {
            const int m = rsel ? m1 : m0;
            if (m >= NTOK) continue;
            const float inv = rsel ? inv1 : inv0;
            const int qs = rsel * 2;
            const bool doconv = (m >= 1);
            __half* rp = atts + (size_t)(b * NTOK + m) * KTOT + h * DH;
#pragma unroll
            for (int t = 0; t < 8; t++) {
                float v0 = O[t][qs] * inv;
                float v1 = O[t][qs + 1] * inv;
                const int d0 = (t >> 1) * 16 + (t & 1) * 8 + qc;
                if (doconv) {
                    uint32_t cw;
                    asm("ld.shared.b32 %0,[%1];" : "=r"(cw)
                        : "r"(Cv + (uint32_t)(m * CVSTRIDE + d0 * 2)));
                    __half2 c2 = *reinterpret_cast<__half2*>(&cw);
                    v0 += __half2float(c2.x);
                    v1 += __half2float(c2.y);
                }
                *(uint32_t*)(rp + d0) = pack2h(v0, v1);
            }
        }
    }
}

/* ---------------- launch --------------------------------------------------- */
extern "C" void kernel_launch(void* const* d_in, const int* in_sizes, int n_in,
                              void* d_out, int out_size)
{
    const float* x      = (const float*)d_in[0];
    const float* W_qkv  = (const float*)d_in[1];
    const float* b_qkv  = (const float*)d_in[2];
    const float* W_proj = (const float*)d_in[3];
    const float* b_proj = (const float*)d_in[4];
    const float* dwc_w  = (const float*)d_in[5];
    const float* dwc_b  = (const float*)d_in[6];
    float* out = (float*)d_out;

    __half *qkv = nullptr, *xs = nullptr, *atts = nullptr, *wqkvs = nullptr, *wprojs = nullptr;
    cudaGetSymbolAddress((void**)&qkv, g_qkv);
    cudaGetSymbolAddress((void**)&xs, g_xs);
    cudaGetSymbolAddress((void**)&atts, g_atts);
    cudaGetSymbolAddress((void**)&wqkvs, g_wqkvs);
    cudaGetSymbolAddress((void**)&wprojs, g_wprojs);

    cudaFuncSetAttribute(attn_mma, cudaFuncAttributeMaxDynamicSharedMemorySize, ASMEM);
    cudaFuncSetAttribute(gemm_mma<__half>, cudaFuncAttributeMaxDynamicSharedMemorySize, GSMEM);
    cudaFuncSetAttribute(gemm_mma<float>, cudaFuncAttributeMaxDynamicSharedMemorySize, GSMEM);

    xpack<<<(M_ROWS * KTOT) / 256, 256>>>(x, xs, M_ROWS * KTOT);
    wpack<<<dim3(QKV_N / 32, KTOT / 32), 256>>>(W_qkv, wqkvs, QKV_N);
    wpack<<<dim3(CDIM / 32, KTOT / 32), 256>>>(W_proj, wprojs, CDIM);

    /* 1) qkv = x @ W_qkv + b_qkv  (fp16 output) */
    gemm_mma<__half><<<dim3(QKV_N / TN, M_ROWS / TM), 64, GSMEM>>>(xs, wqkvs, b_qkv, qkv, QKV_N);

    /* 2) attention + precomputed depthwise conv -> atts (fp16) */
    attn_mma<<<BATCH * HEADS, 128, ASMEM>>>(qkv, dwc_w, dwc_b, atts);

    /* 3) out = (attn+conv) @ W_proj + b_proj  (fp32 output) */
    gemm_mma<float><<<dim3(CDIM / TN, M_ROWS / TM), 64, GSMEM>>>(atts, wprojs, b_proj, out, CDIM);
}